// round 16
// baseline (speedup 1.0000x reference)
#include <cuda_runtime.h>
#include <cuda_bf16.h>
#include <cstdint>

// Fixed problem shape: N=100000, E=1250000, IN=6, HID=64.
#define NMAX 100352
#define HID 64

// ---------------- scratch ----------------
// aux: one 32B sector per node: [0]=deg(int), [2]=w(float), [3]=dis(float)
__device__ __align__(32) int   g_aux [NMAX * 8];
__device__ __align__(32) __nv_bfloat16 g_aggb[NMAX * 16]; // 32B/node, first 16B = bf16x8 agg
// gather-only (dense):
__device__ __align__(16) __nv_bfloat16 g_disb[NMAX];      // bf16 dis for scatter
__device__ __align__(16) __nv_bfloat16 g_xsb [NMAX * 8];  // 16B/row packed bf16 features
__device__ __align__(16) double g_u   [HID];
__device__ int g_cnt;                                     // u completion counter (self-resets)

// per-block dtype detect: int64 LE edge data viewed as int32 has odd words all zero
__device__ __forceinline__ int detect64(const int* ei32, int* sflag, int tid) {
    if (tid == 0) {
        int is64 = 1;
        for (int k = 1; k < 128; k += 2)
            if (__ldg(&ei32[k]) != 0) { is64 = 0; break; }
        *sflag = is64;
    }
    __syncthreads();
    return *sflag;
}

// ---------------- degree count (4 edges/thread) ----------------
__global__ __launch_bounds__(256, 8)
void degcnt_kernel(const int* __restrict__ ei32, int E) {
    __shared__ int sflag;
    int is64 = detect64(ei32, &sflag, threadIdx.x);
    long long t = blockIdx.x * blockDim.x + threadIdx.x;
    long long e0 = t * 4;
    if (e0 >= E) return;
    if (e0 + 4 <= E) {
        int d[4];
        if (is64) {
            const int4* p = (const int4*)(ei32 + 2ll * E) + t * 2;
            int4 a = __ldg(p), b = __ldg(p + 1);
            d[0] = a.x; d[1] = a.z; d[2] = b.x; d[3] = b.z;
        } else {
            int4 a = __ldg((const int4*)(ei32 + (long long)E) + t);
            d[0] = a.x; d[1] = a.y; d[2] = a.z; d[3] = a.w;
        }
#pragma unroll
        for (int q = 0; q < 4; ++q) atomicAdd(&g_aux[(size_t)d[q] * 8], 1);
    } else {
        for (long long e = e0; e < E; ++e) {
            int dd = is64 ? __ldg(&ei32[2ll * (E + e)]) : __ldg(&ei32[E + e]);
            atomicAdd(&g_aux[(size_t)dd * 8], 1);
        }
    }
}

// ---------------- prep: dis, xsb, aggb=xsb, aux cleanup, zero u ----------------
__global__ void prep_kernel(const float* __restrict__ x, int n) {
    int i = blockIdx.x * blockDim.x + threadIdx.x;
    if (i < HID) g_u[i] = 0.0;
    if (i >= n) return;
    int* aux = g_aux + (size_t)i * 8;
    int dg = aux[0];
    float d = rsqrtf((float)dg + 1.0f);
    aux[0] = 0;                         // self-clean for next replay
    ((float*)aux)[2] = 0.0f;            // w = 0
    ((float*)aux)[3] = d;               // dis (8B-aligned pair with w)
    g_disb[i] = __float2bfloat16(d);
    const float* xi = x + (size_t)i * 6;
    __nv_bfloat162 p0 = __floats2bfloat162_rn(xi[0] * d, xi[1] * d);
    __nv_bfloat162 p1 = __floats2bfloat162_rn(xi[2] * d, xi[3] * d);
    __nv_bfloat162 p2 = __floats2bfloat162_rn(xi[4] * d, xi[5] * d);
    uint4 pk;
    pk.x = *reinterpret_cast<uint32_t*>(&p0);
    pk.y = *reinterpret_cast<uint32_t*>(&p1);
    pk.z = *reinterpret_cast<uint32_t*>(&p2);
    pk.w = 0u;
    ((uint4*)g_xsb)[i] = pk;
    ((uint4*)g_aggb)[(size_t)i * 2] = pk;   // self-loop pre-seeded
}

// ---------------- edge scatter (4 edges/thread) ----------------
__device__ __forceinline__ void scat1(int src, int dst) {
    uint4 v = __ldg(((const uint4*)g_xsb) + src);
    float dd = __bfloat162float(__ldg(&g_disb[dst]));
    __nv_bfloat16* p = g_aggb + (size_t)dst * 16;
    asm volatile("red.global.add.noftz.v4.bf16x2 [%0], {%1,%2,%3,%4};"
                 :: "l"(p), "r"(v.x), "r"(v.y), "r"(v.z), "r"(v.w) : "memory");
    atomicAdd(&((float*)g_aux)[(size_t)src * 8 + 2], dd);
}

__global__ __launch_bounds__(256, 8)
void scatter_kernel(const int* __restrict__ ei32, int E) {
    __shared__ int sflag;
    int is64 = detect64(ei32, &sflag, threadIdx.x);
    long long t = blockIdx.x * blockDim.x + threadIdx.x;
    long long e0 = t * 4;
    if (e0 >= E) return;
    if (e0 + 4 <= E) {
        int s[4], d[4];
        if (is64) {
            const int4* ps = (const int4*)ei32 + t * 2;
            const int4* pd = (const int4*)(ei32 + 2ll * E) + t * 2;
            int4 a = __ldg(ps), b = __ldg(ps + 1);
            int4 c = __ldg(pd), e = __ldg(pd + 1);
            s[0] = a.x; s[1] = a.z; s[2] = b.x; s[3] = b.z;
            d[0] = c.x; d[1] = c.z; d[2] = e.x; d[3] = e.z;
        } else {
            int4 a = __ldg((const int4*)ei32 + t);
            int4 c = __ldg((const int4*)(ei32 + (long long)E) + t);
            s[0] = a.x; s[1] = a.y; s[2] = a.z; s[3] = a.w;
            d[0] = c.x; d[1] = c.y; d[2] = c.z; d[3] = c.w;
        }
        uint4 v[4];
        float dd[4];
#pragma unroll
        for (int q = 0; q < 4; ++q) v[q] = __ldg(((const uint4*)g_xsb) + s[q]);
#pragma unroll
        for (int q = 0; q < 4; ++q) dd[q] = __bfloat162float(__ldg(&g_disb[d[q]]));
#pragma unroll
        for (int q = 0; q < 4; ++q) {
            __nv_bfloat16* p = g_aggb + (size_t)d[q] * 16;
            asm volatile("red.global.add.noftz.v4.bf16x2 [%0], {%1,%2,%3,%4};"
                         :: "l"(p), "r"(v[q].x), "r"(v[q].y), "r"(v[q].z), "r"(v[q].w) : "memory");
            atomicAdd(&((float*)g_aux)[(size_t)s[q] * 8 + 2], dd[q]);
        }
    } else {
        for (long long e = e0; e < E; ++e) {
            int ss, dd;
            if (is64) { ss = __ldg(&ei32[2ll * e]); dd = __ldg(&ei32[2ll * (E + e)]); }
            else      { ss = __ldg(&ei32[e]);       dd = __ldg(&ei32[E + e]); }
            scat1(ss, dd);
        }
    }
}

// ---------------- fused u + final: warp-per-node-group, 2 columns/thread ----------------
// u[j] = sum_i c[i]*relu( (dis[i]*aggb[i]) . W1[:,j] + b1[j] ),  c = dis*(w+dis)
__global__ __launch_bounds__(256)
void u_kernel(const float* __restrict__ W1, const float* __restrict__ b1,
              const float* __restrict__ W2, const float* __restrict__ b2,
              const float* __restrict__ Wfc, const float* __restrict__ bfc,
              float* __restrict__ out, int n) {
    __shared__ float sred[8 * HID];
    __shared__ int isLast;
    int tid = threadIdx.x;
    int l   = tid & 31;          // lane: owns columns l and l+32
    int w   = tid >> 5;          // warp in block: 0..7
    float bA = __ldg(&b1[l]);
    float bB = __ldg(&b1[l + 32]);
    float wA[6], wB[6];
#pragma unroll
    for (int k = 0; k < 6; ++k) {
        wA[k] = __ldg(&W1[k * HID + l]);
        wB[k] = __ldg(&W1[k * HID + l + 32]);
    }
    float uA = 0.0f, uB = 0.0f;
    const float* auxf = (const float*)g_aux;
    int gw = blockIdx.x * 8 + w;
    int NW = gridDim.x * 8;
    for (int i0 = gw * 4; i0 < n; i0 += NW * 4) {
        int m = n - i0; if (m > 4) m = 4;
        uint4  ap[4];
        float2 wd[4];
#pragma unroll
        for (int q = 0; q < 4; ++q) {       // issue ALL loads first (MLP=8/warp)
            int i = i0 + ((q < m) ? q : 0);
            ap[q] = __ldg(((const uint4*)g_aggb) + (size_t)i * 2);
            wd[q] = __ldg((const float2*)(auxf + (size_t)i * 8 + 2));
        }
#pragma unroll
        for (int q = 0; q < 4; ++q) {
            if (q < m) {
                float d = wd[q].y;
                float2 a01 = __bfloat1622float2(*reinterpret_cast<const __nv_bfloat162*>(&ap[q].x));
                float2 a23 = __bfloat1622float2(*reinterpret_cast<const __nv_bfloat162*>(&ap[q].y));
                float2 a45 = __bfloat1622float2(*reinterpret_cast<const __nv_bfloat162*>(&ap[q].z));
                float v0 = a01.x * d, v1 = a01.y * d, v2 = a23.x * d;
                float v3 = a23.y * d, v4 = a45.x * d, v5 = a45.y * d;
                float hA = bA, hB = bB;
                hA = fmaf(v0, wA[0], hA); hB = fmaf(v0, wB[0], hB);
                hA = fmaf(v1, wA[1], hA); hB = fmaf(v1, wB[1], hB);
                hA = fmaf(v2, wA[2], hA); hB = fmaf(v2, wB[2], hB);
                hA = fmaf(v3, wA[3], hA); hB = fmaf(v3, wB[3], hB);
                hA = fmaf(v4, wA[4], hA); hB = fmaf(v4, wB[4], hB);
                hA = fmaf(v5, wA[5], hA); hB = fmaf(v5, wB[5], hB);
                hA = fmaxf(hA, 0.0f);     hB = fmaxf(hB, 0.0f);
                float c = d * (wd[q].x + d);
                uA = fmaf(c, hA, uA);     uB = fmaf(c, hB, uB);
            }
        }
    }
    sred[w * HID + l]      = uA;
    sred[w * HID + l + 32] = uB;
    __syncthreads();
    if (tid < HID) {
        double s = 0.0;
#pragma unroll
        for (int g = 0; g < 8; ++g) s += (double)sred[g * HID + tid];
        atomicAdd(&g_u[tid], s);
    }
    __threadfence();
    __syncthreads();
    if (tid == 0) {
        int prev = atomicAdd(&g_cnt, 1);
        isLast = (prev == gridDim.x - 1);
        if (isLast) g_cnt = 0;
    }
    __syncthreads();
    if (!isLast) return;
    __threadfence();
    __shared__ double sf[HID];
    if (tid < HID) {
        double acc = 0.0;
#pragma unroll 8
        for (int k = 0; k < HID; ++k)
            acc += g_u[k] * (double)W2[k * HID + tid];
        double tt = acc / (double)n + (double)b2[tid];
        sf[tid] = tt * (double)Wfc[tid];
    }
    __syncthreads();
    if (tid < 32) {
        double v = sf[tid] + sf[tid + 32];
#pragma unroll
        for (int o = 16; o; o >>= 1) v += __shfl_down_sync(0xffffffff, v, o);
        if (tid == 0) {
            double z = v + (double)bfc[0];
            out[0] = (float)(1.0 / (1.0 + exp(-z)));
        }
    }
}

// ================================================================ launch
extern "C" void kernel_launch(void* const* d_in, const int* in_sizes, int n_in,
                              void* d_out, int out_size) {
    const float* x   = (const float*)d_in[0];
    const int*   ei  = (const int*)d_in[1];   // int32 OR int64 (auto-detected per block)
    const float* W1  = (const float*)d_in[2];
    const float* b1  = (const float*)d_in[3];
    const float* W2  = (const float*)d_in[4];
    const float* b2  = (const float*)d_in[5];
    const float* Wfc = (const float*)d_in[6];
    const float* bfc = (const float*)d_in[7];
    float* out = (float*)d_out;

    int n = in_sizes[0] / 6;      // 100000
    int E = in_sizes[1] / 2;      // 1250000
    int nq = (E + 3) / 4;         // edge quads

    degcnt_kernel<<<(nq + 255) / 256, 256>>>(ei, E);
    prep_kernel<<<(n + 255) / 256, 256>>>(x, n);
    scatter_kernel<<<(nq + 255) / 256, 256>>>(ei, E);
    u_kernel<<<1024, 256>>>(W1, b1, W2, b2, Wfc, bfc, out, n);
}

// round 17
// speedup vs baseline: 1.0216x; 1.0216x over previous
#include <cuda_runtime.h>
#include <cuda_bf16.h>
#include <cstdint>

// Fixed problem shape: N=100000, E=1250000, IN=6, HID=64.
#define NMAX 100352
#define HID 64

// ---------------- scratch ----------------
// g_nd: ONE 32B sector per node (all per-node RMW + read state):
//   uint[0..3] = bf16x8 agg row (red.v4.bf16x2 target; self-loop pre-seeded)
//   uint[4]    = w (float, scatter src-accumulator)
//   uint[5]    = dis (fp32)
//   uint[6]    = deg (int, degcnt target; cleared by prep's vector store)
//   uint[7]    = pad
__device__ __align__(32) unsigned g_nd[NMAX * 8];
// gather-only (dense):
__device__ __align__(16) __nv_bfloat16 g_disb[NMAX];      // bf16 dis for scatter dst-gather
__device__ __align__(16) __nv_bfloat16 g_xsb [NMAX * 8];  // 16B/row packed bf16 features
__device__ __align__(16) double g_u   [HID];
__device__ int g_cnt;                                     // u completion counter (self-resets)

// per-block dtype detect: int64 LE edge data viewed as int32 has odd words all zero
__device__ __forceinline__ int detect64(const int* ei32, int* sflag, int tid) {
    if (tid == 0) {
        int is64 = 1;
        for (int k = 1; k < 128; k += 2)
            if (__ldg(&ei32[k]) != 0) { is64 = 0; break; }
        *sflag = is64;
    }
    __syncthreads();
    return *sflag;
}

// ---------------- degree count (4 edges/thread) ----------------
__global__ __launch_bounds__(256, 8)
void degcnt_kernel(const int* __restrict__ ei32, int E) {
    __shared__ int sflag;
    int is64 = detect64(ei32, &sflag, threadIdx.x);
    long long t = blockIdx.x * blockDim.x + threadIdx.x;
    long long e0 = t * 4;
    if (e0 >= E) return;
    if (e0 + 4 <= E) {
        int d[4];
        if (is64) {
            const int4* p = (const int4*)(ei32 + 2ll * E) + t * 2;
            int4 a = __ldg(p), b = __ldg(p + 1);
            d[0] = a.x; d[1] = a.z; d[2] = b.x; d[3] = b.z;
        } else {
            int4 a = __ldg((const int4*)(ei32 + (long long)E) + t);
            d[0] = a.x; d[1] = a.y; d[2] = a.z; d[3] = a.w;
        }
#pragma unroll
        for (int q = 0; q < 4; ++q)
            atomicAdd((int*)(g_nd + (size_t)d[q] * 8 + 6), 1);
    } else {
        for (long long e = e0; e < E; ++e) {
            int dd = is64 ? __ldg(&ei32[2ll * (E + e)]) : __ldg(&ei32[E + e]);
            atomicAdd((int*)(g_nd + (size_t)dd * 8 + 6), 1);
        }
    }
}

// ---------------- prep: build node row + dense gather arrays, zero u ----------------
__global__ void prep_kernel(const float* __restrict__ x, int n) {
    int i = blockIdx.x * blockDim.x + threadIdx.x;
    if (i < HID) g_u[i] = 0.0;
    if (i >= n) return;
    unsigned* row = g_nd + (size_t)i * 8;
    int dg = ((int*)row)[6];
    float d = rsqrtf((float)dg + 1.0f);
    const float* xi = x + (size_t)i * 6;
    __nv_bfloat162 p0 = __floats2bfloat162_rn(xi[0] * d, xi[1] * d);
    __nv_bfloat162 p1 = __floats2bfloat162_rn(xi[2] * d, xi[3] * d);
    __nv_bfloat162 p2 = __floats2bfloat162_rn(xi[4] * d, xi[5] * d);
    uint4 pk;
    pk.x = *reinterpret_cast<uint32_t*>(&p0);
    pk.y = *reinterpret_cast<uint32_t*>(&p1);
    pk.z = *reinterpret_cast<uint32_t*>(&p2);
    pk.w = 0u;
    uint4 meta;
    meta.x = __float_as_uint(0.0f);   // w = 0
    meta.y = __float_as_uint(d);      // dis
    meta.z = 0u;                      // deg cleared for next replay
    meta.w = 0u;
    ((uint4*)row)[0] = pk;            // agg seeded with self-loop
    ((uint4*)row)[1] = meta;
    g_disb[i] = __float2bfloat16(d);
    ((uint4*)g_xsb)[i] = pk;
}

// ---------------- edge scatter (4 edges/thread) ----------------
__device__ __forceinline__ void scat1(int src, int dst) {
    uint4 v = __ldg(((const uint4*)g_xsb) + src);
    float dd = __bfloat162float(__ldg(&g_disb[dst]));
    unsigned* p = g_nd + (size_t)dst * 8;
    asm volatile("red.global.add.noftz.v4.bf16x2 [%0], {%1,%2,%3,%4};"
                 :: "l"(p), "r"(v.x), "r"(v.y), "r"(v.z), "r"(v.w) : "memory");
    atomicAdd((float*)(g_nd + (size_t)src * 8 + 4), dd);
}

__global__ __launch_bounds__(256, 8)
void scatter_kernel(const int* __restrict__ ei32, int E) {
    __shared__ int sflag;
    int is64 = detect64(ei32, &sflag, threadIdx.x);
    long long t = blockIdx.x * blockDim.x + threadIdx.x;
    long long e0 = t * 4;
    if (e0 >= E) return;
    if (e0 + 4 <= E) {
        int s[4], d[4];
        if (is64) {
            const int4* ps = (const int4*)ei32 + t * 2;
            const int4* pd = (const int4*)(ei32 + 2ll * E) + t * 2;
            int4 a = __ldg(ps), b = __ldg(ps + 1);
            int4 c = __ldg(pd), e = __ldg(pd + 1);
            s[0] = a.x; s[1] = a.z; s[2] = b.x; s[3] = b.z;
            d[0] = c.x; d[1] = c.z; d[2] = e.x; d[3] = e.z;
        } else {
            int4 a = __ldg((const int4*)ei32 + t);
            int4 c = __ldg((const int4*)(ei32 + (long long)E) + t);
            s[0] = a.x; s[1] = a.y; s[2] = a.z; s[3] = a.w;
            d[0] = c.x; d[1] = c.y; d[2] = c.z; d[3] = c.w;
        }
        uint4 v[4];
        float dd[4];
#pragma unroll
        for (int q = 0; q < 4; ++q) v[q] = __ldg(((const uint4*)g_xsb) + s[q]);
#pragma unroll
        for (int q = 0; q < 4; ++q) dd[q] = __bfloat162float(__ldg(&g_disb[d[q]]));
#pragma unroll
        for (int q = 0; q < 4; ++q) {
            unsigned* p = g_nd + (size_t)d[q] * 8;
            asm volatile("red.global.add.noftz.v4.bf16x2 [%0], {%1,%2,%3,%4};"
                         :: "l"(p), "r"(v[q].x), "r"(v[q].y), "r"(v[q].z), "r"(v[q].w) : "memory");
            atomicAdd((float*)(g_nd + (size_t)s[q] * 8 + 4), dd[q]);
        }
    } else {
        for (long long e = e0; e < E; ++e) {
            int ss, dd;
            if (is64) { ss = __ldg(&ei32[2ll * e]); dd = __ldg(&ei32[2ll * (E + e)]); }
            else      { ss = __ldg(&ei32[e]);       dd = __ldg(&ei32[E + e]); }
            scat1(ss, dd);
        }
    }
}

// ---------------- fused u + final: warp-per-4-nodes, 2 columns/thread, 1 sector/node ----
// u[j] = sum_i c[i]*relu( (dis[i]*agg[i]) . W1[:,j] + b1[j] ),  c = dis*(w+dis)
__global__ __launch_bounds__(256)
void u_kernel(const float* __restrict__ W1, const float* __restrict__ b1,
              const float* __restrict__ W2, const float* __restrict__ b2,
              const float* __restrict__ Wfc, const float* __restrict__ bfc,
              float* __restrict__ out, int n) {
    __shared__ float sred[8 * HID];
    __shared__ int isLast;
    int tid = threadIdx.x;
    int l   = tid & 31;          // lane: owns columns l and l+32
    int w   = tid >> 5;          // warp in block: 0..7
    float bA = __ldg(&b1[l]);
    float bB = __ldg(&b1[l + 32]);
    float wA[6], wB[6];
#pragma unroll
    for (int k = 0; k < 6; ++k) {
        wA[k] = __ldg(&W1[k * HID + l]);
        wB[k] = __ldg(&W1[k * HID + l + 32]);
    }
    float uA = 0.0f, uB = 0.0f;
    int gw = blockIdx.x * 8 + w;
    int NW = gridDim.x * 8;
    for (int i0 = gw * 4; i0 < n; i0 += NW * 4) {
        int m = n - i0; if (m > 4) m = 4;
        uint4  ap[4];
        float2 wd[4];
#pragma unroll
        for (int q = 0; q < 4; ++q) {       // issue ALL loads first; both hit ONE sector/node
            int i = i0 + ((q < m) ? q : 0);
            ap[q] = __ldg(((const uint4*)g_nd) + (size_t)i * 2);
            wd[q] = __ldg((const float2*)(g_nd + (size_t)i * 8 + 4));
        }
#pragma unroll
        for (int q = 0; q < 4; ++q) {
            if (q < m) {
                float d = wd[q].y;
                float2 a01 = __bfloat1622float2(*reinterpret_cast<const __nv_bfloat162*>(&ap[q].x));
                float2 a23 = __bfloat1622float2(*reinterpret_cast<const __nv_bfloat162*>(&ap[q].y));
                float2 a45 = __bfloat1622float2(*reinterpret_cast<const __nv_bfloat162*>(&ap[q].z));
                float v0 = a01.x * d, v1 = a01.y * d, v2 = a23.x * d;
                float v3 = a23.y * d, v4 = a45.x * d, v5 = a45.y * d;
                float hA = bA, hB = bB;
                hA = fmaf(v0, wA[0], hA); hB = fmaf(v0, wB[0], hB);
                hA = fmaf(v1, wA[1], hA); hB = fmaf(v1, wB[1], hB);
                hA = fmaf(v2, wA[2], hA); hB = fmaf(v2, wB[2], hB);
                hA = fmaf(v3, wA[3], hA); hB = fmaf(v3, wB[3], hB);
                hA = fmaf(v4, wA[4], hA); hB = fmaf(v4, wB[4], hB);
                hA = fmaf(v5, wA[5], hA); hB = fmaf(v5, wB[5], hB);
                hA = fmaxf(hA, 0.0f);     hB = fmaxf(hB, 0.0f);
                float c = d * (wd[q].x + d);
                uA = fmaf(c, hA, uA);     uB = fmaf(c, hB, uB);
            }
        }
    }
    sred[w * HID + l]      = uA;
    sred[w * HID + l + 32] = uB;
    __syncthreads();
    if (tid < HID) {
        double s = 0.0;
#pragma unroll
        for (int g = 0; g < 8; ++g) s += (double)sred[g * HID + tid];
        atomicAdd(&g_u[tid], s);
    }
    __threadfence();
    __syncthreads();
    if (tid == 0) {
        int prev = atomicAdd(&g_cnt, 1);
        isLast = (prev == gridDim.x - 1);
        if (isLast) g_cnt = 0;
    }
    __syncthreads();
    if (!isLast) return;
    __threadfence();
    __shared__ double sf[HID];
    if (tid < HID) {
        double acc = 0.0;
#pragma unroll 8
        for (int k = 0; k < HID; ++k)
            acc += g_u[k] * (double)W2[k * HID + tid];
        double tt = acc / (double)n + (double)b2[tid];
        sf[tid] = tt * (double)Wfc[tid];
    }
    __syncthreads();
    if (tid < 32) {
        double v = sf[tid] + sf[tid + 32];
#pragma unroll
        for (int o = 16; o; o >>= 1) v += __shfl_down_sync(0xffffffff, v, o);
        if (tid == 0) {
            double z = v + (double)bfc[0];
            out[0] = (float)(1.0 / (1.0 + exp(-z)));
        }
    }
}

// ================================================================ launch
extern "C" void kernel_launch(void* const* d_in, const int* in_sizes, int n_in,
                              void* d_out, int out_size) {
    const float* x   = (const float*)d_in[0];
    const int*   ei  = (const int*)d_in[1];   // int32 OR int64 (auto-detected per block)
    const float* W1  = (const float*)d_in[2];
    const float* b1  = (const float*)d_in[3];
    const float* W2  = (const float*)d_in[4];
    const float* b2  = (const float*)d_in[5];
    const float* Wfc = (const float*)d_in[6];
    const float* bfc = (const float*)d_in[7];
    float* out = (float*)d_out;

    int n = in_sizes[0] / 6;      // 100000
    int E = in_sizes[1] / 2;      // 1250000
    int nq = (E + 3) / 4;         // edge quads

    degcnt_kernel<<<(nq + 255) / 256, 256>>>(ei, E);
    prep_kernel<<<(n + 255) / 256, 256>>>(x, n);
    scatter_kernel<<<(nq + 255) / 256, 256>>>(ei, E);
    u_kernel<<<1024, 256>>>(W1, b1, W2, b2, Wfc, bfc, out, n);
}